// round 1
// baseline (speedup 1.0000x reference)
#include <cuda_runtime.h>
#include <cuda_bf16.h>
#include <cstdint>

// Problem dims
#define BB   256
#define TT   512
#define EMB  128
#define HID  256
#define NCLS 32000

// Scratch: bf16 h0_last [B][HID]
__device__ __nv_bfloat16 g_h0[BB * HID];

// ---------------------------------------------------------------------------
// Kernel A: h0_last = gates(E @ {U_i,U_c,U_o} + b)  (layer-0 LSTM, no recurrence)
// 32 blocks x 256 threads; each block handles 8 batch rows, each thread one h.
// ---------------------------------------------------------------------------
__global__ void __launch_bounds__(256) lstm0_kernel(
    const int* __restrict__ X, const float* __restrict__ C_table,
    const float* __restrict__ U_i, const float* __restrict__ b_i,
    const float* __restrict__ U_c, const float* __restrict__ b_c,
    const float* __restrict__ U_o, const float* __restrict__ b_o)
{
    __shared__ float Esh[8][EMB];
    const int b0 = blockIdx.x * 8;
    const int t  = threadIdx.x;

    // Gather the 8 embedding rows for the LAST timestep
    for (int r = 0; r < 8; r++) {
        int tok = X[(b0 + r) * TT + (TT - 1)];
        if (t < EMB) Esh[r][t] = C_table[tok * EMB + t];
    }
    __syncthreads();

    const int h = t;  // hidden unit owned by this thread
    float ai[8], ac[8], ao[8];
#pragma unroll
    for (int r = 0; r < 8; r++) { ai[r] = 0.f; ac[r] = 0.f; ao[r] = 0.f; }

#pragma unroll 4
    for (int e = 0; e < EMB; e++) {
        float ui = U_i[e * HID + h];
        float uc = U_c[e * HID + h];
        float uo = U_o[e * HID + h];
#pragma unroll
        for (int r = 0; r < 8; r++) {
            float ev = Esh[r][e];
            ai[r] = fmaf(ev, ui, ai[r]);
            ac[r] = fmaf(ev, uc, ac[r]);
            ao[r] = fmaf(ev, uo, ao[r]);
        }
    }

    const float bi = b_i[h], bc = b_c[h], bo = b_o[h];
#pragma unroll
    for (int r = 0; r < 8; r++) {
        float i0 = 1.f / (1.f + expf(-(ai[r] + bi)));
        float g0 = tanhf(ac[r] + bc);
        float o0 = 1.f / (1.f + expf(-(ao[r] + bo)));
        float c0 = i0 * g0;
        float h0 = o0 * tanhf(c0);
        g_h0[(b0 + r) * HID + h] = __float2bfloat16(h0);
    }
}

// ---------------------------------------------------------------------------
// Kernel B: out[B][NCLS] = h0 @ W_w^T + b_out   via bf16 mma.sync (HMMA)
// 500 blocks (64 classes each) x 256 threads (8 warps).
// Each block spans ALL 256 batch rows -> W_w is read from DRAM exactly once.
// Warp w computes a 32(m) x 64(n) tile: 2 m-frags x 8 n-frags of m16n8k16.
// ---------------------------------------------------------------------------
#define WPAD 132  // smem words per W row (128 data + 4 pad -> bank = 4*g+tg, conflict-free)

__device__ __forceinline__ void mma_bf16(float c[4], const uint32_t a[4],
                                         uint32_t b0, uint32_t b1)
{
    asm volatile(
        "mma.sync.aligned.m16n8k16.row.col.f32.bf16.bf16.f32 "
        "{%0,%1,%2,%3}, {%4,%5,%6,%7}, {%8,%9}, {%0,%1,%2,%3};"
        : "+f"(c[0]), "+f"(c[1]), "+f"(c[2]), "+f"(c[3])
        : "r"(a[0]), "r"(a[1]), "r"(a[2]), "r"(a[3]), "r"(b0), "r"(b1));
}

__global__ void __launch_bounds__(256) logits_kernel(
    const float* __restrict__ W, const float* __restrict__ b_out,
    float* __restrict__ out)
{
    __shared__ uint32_t Wsh[64 * WPAD];  // bf16x2 words, 64 class rows x 128 k-words (+pad)

    const int n_base = blockIdx.x * 64;
    const int tid = threadIdx.x;

    // Stage W chunk [64 x 256] fp32 -> bf16 smem. Chunk is contiguous in gmem.
    {
        const float2* W2 = reinterpret_cast<const float2*>(W + (size_t)n_base * HID);
#pragma unroll 4
        for (int i = tid; i < 64 * 128; i += 256) {
            float2 v = W2[i];
            __nv_bfloat162 bv = __floats2bfloat162_rn(v.x, v.y);
            int row = i >> 7;
            int col = i & 127;
            Wsh[row * WPAD + col] = *reinterpret_cast<uint32_t*>(&bv);
        }
    }
    __syncthreads();

    const uint32_t* H = reinterpret_cast<const uint32_t*>(g_h0);  // [256][128] bf16x2 words
    const int warp = tid >> 5;
    const int lane = tid & 31;
    const int g  = lane >> 2;   // groupID
    const int tg = lane & 3;    // thread in group
    const int m0 = warp * 32;   // this warp's batch-row base

    float c[2][8][4];
#pragma unroll
    for (int mf = 0; mf < 2; mf++)
#pragma unroll
        for (int nf = 0; nf < 8; nf++)
#pragma unroll
            for (int i = 0; i < 4; i++) c[mf][nf][i] = 0.f;

#pragma unroll 2
    for (int ks = 0; ks < 16; ks++) {
        const int kw = ks * 8;  // k-word base (k = ks*16)
        uint32_t a[2][4];
#pragma unroll
        for (int mf = 0; mf < 2; mf++) {
            int r0 = m0 + mf * 16 + g;
            a[mf][0] = H[(r0    ) * 128 + kw + tg];
            a[mf][1] = H[(r0 + 8) * 128 + kw + tg];
            a[mf][2] = H[(r0    ) * 128 + kw + 4 + tg];
            a[mf][3] = H[(r0 + 8) * 128 + kw + 4 + tg];
        }
#pragma unroll
        for (int nf = 0; nf < 8; nf++) {
            uint32_t b0r = Wsh[(nf * 8 + g) * WPAD + kw + tg];
            uint32_t b1r = Wsh[(nf * 8 + g) * WPAD + kw + 4 + tg];
            mma_bf16(c[0][nf], a[0], b0r, b1r);
            mma_bf16(c[1][nf], a[1], b0r, b1r);
        }
    }

    // Epilogue: add b_out, float2 stores
#pragma unroll
    for (int nf = 0; nf < 8; nf++) {
        const int n = n_base + nf * 8 + tg * 2;
        const float2 bo = *reinterpret_cast<const float2*>(b_out + n);
#pragma unroll
        for (int mf = 0; mf < 2; mf++) {
            int r0 = m0 + mf * 16 + g;
            float2 v0 = make_float2(c[mf][nf][0] + bo.x, c[mf][nf][1] + bo.y);
            float2 v1 = make_float2(c[mf][nf][2] + bo.x, c[mf][nf][3] + bo.y);
            *reinterpret_cast<float2*>(out + (size_t)(r0    ) * NCLS + n) = v0;
            *reinterpret_cast<float2*>(out + (size_t)(r0 + 8) * NCLS + n) = v1;
        }
    }
}

// ---------------------------------------------------------------------------
extern "C" void kernel_launch(void* const* d_in, const int* in_sizes, int n_in,
                              void* d_out, int out_size)
{
    const int*   X       = (const int*)  d_in[0];
    const float* C_table = (const float*)d_in[1];
    const float* U_i     = (const float*)d_in[2];
    const float* b_i     = (const float*)d_in[4];
    const float* U_c     = (const float*)d_in[8];
    const float* b_c     = (const float*)d_in[10];
    const float* U_o     = (const float*)d_in[11];
    const float* b_o     = (const float*)d_in[13];
    const float* W_w     = (const float*)d_in[26];
    const float* b_out   = (const float*)d_in[27];
    float* out = (float*)d_out;

    lstm0_kernel<<<32, 256>>>(X, C_table, U_i, b_i, U_c, b_c, U_o, b_o);
    logits_kernel<<<NCLS / 64, 256>>>(W_w, b_out, out);
}

// round 2
// speedup vs baseline: 1.2799x; 1.2799x over previous
#include <cuda_runtime.h>
#include <cuda_bf16.h>
#include <cstdint>

// Problem dims
#define BB   256
#define TT   512
#define EMB  128
#define HID  256
#define NCLS 32000

// Scratch: H pre-swizzled into mma A-fragment order.
// Layout: [m_tile(16)][ks(16)][lane(32)] of uint4 = {a0,a1,a2,a3} bf16x2 words,
// where for tile rows R=m_tile*16, k-words KW=ks*8, lane l (g=l/4, tg=l%4):
//   a0 = word(R+g,   KW+tg)   a1 = word(R+8+g, KW+tg)
//   a2 = word(R+g,   KW+4+tg) a3 = word(R+8+g, KW+4+tg)
__device__ uint4 g_h0p[16 * 16 * 32];   // 128 KB

// ---------------------------------------------------------------------------
// Kernel A: h0_last = gates(E @ {U_i,U_c,U_o} + b), written pre-swizzled.
// 32 blocks x 256 threads; each block handles 8 batch rows, each thread one h.
// ---------------------------------------------------------------------------
__global__ void __launch_bounds__(256) lstm0_kernel(
    const int* __restrict__ X, const float* __restrict__ C_table,
    const float* __restrict__ U_i, const float* __restrict__ b_i,
    const float* __restrict__ U_c, const float* __restrict__ b_c,
    const float* __restrict__ U_o, const float* __restrict__ b_o)
{
    __shared__ float Esh[8][EMB];
    __shared__ float Hsh[8][HID];
    const int b0 = blockIdx.x * 8;
    const int t  = threadIdx.x;

    for (int r = 0; r < 8; r++) {
        int tok = X[(b0 + r) * TT + (TT - 1)];
        if (t < EMB) Esh[r][t] = C_table[tok * EMB + t];
    }
    __syncthreads();

    const int h = t;
    float ai[8], ac[8], ao[8];
#pragma unroll
    for (int r = 0; r < 8; r++) { ai[r] = 0.f; ac[r] = 0.f; ao[r] = 0.f; }

#pragma unroll 4
    for (int e = 0; e < EMB; e++) {
        float ui = U_i[e * HID + h];
        float uc = U_c[e * HID + h];
        float uo = U_o[e * HID + h];
#pragma unroll
        for (int r = 0; r < 8; r++) {
            float ev = Esh[r][e];
            ai[r] = fmaf(ev, ui, ai[r]);
            ac[r] = fmaf(ev, uc, ac[r]);
            ao[r] = fmaf(ev, uo, ao[r]);
        }
    }

    const float bi = b_i[h], bc = b_c[h], bo = b_o[h];
#pragma unroll
    for (int r = 0; r < 8; r++) {
        float i0 = 1.f / (1.f + expf(-(ai[r] + bi)));
        float g0 = tanhf(ac[r] + bc);
        float o0 = 1.f / (1.f + expf(-(ao[r] + bo)));
        float c0 = i0 * g0;
        Hsh[r][h] = o0 * tanhf(c0);
    }
    __syncthreads();

    // Pack into fragment layout. 8 rows x 128 bf16x2 words = 1024 words; 4/thread.
    uint32_t* Hw = reinterpret_cast<uint32_t*>(g_h0p);
#pragma unroll
    for (int j = 0; j < 4; j++) {
        int idx = t + 256 * j;          // 0..1023
        int r   = idx >> 7;             // local row 0..7
        int w   = idx & 127;            // k-word 0..127
        int gr  = b0 + r;               // global row
        int m_tile = gr >> 4;
        int local  = gr & 15;
        int g      = local & 7;
        int comp_r = local >> 3;        // 0 if lower half of 16-row tile, 1 if upper
        int ks     = w >> 3;
        int ww     = w & 7;
        int tg     = ww & 3;
        int comp_k = (ww >> 2) << 1;    // 0 or 2
        int lane   = g * 4 + tg;
        __nv_bfloat162 bv = __floats2bfloat162_rn(Hsh[r][2 * w], Hsh[r][2 * w + 1]);
        Hw[((((m_tile * 16) + ks) * 32 + lane) << 2) + (comp_r + comp_k)] =
            *reinterpret_cast<uint32_t*>(&bv);
    }
}

// ---------------------------------------------------------------------------
// Kernel B: out[B][NCLS] = h0 @ W_w^T + b_out  via bf16 mma.sync
// 500 blocks (64 classes) x 256 threads (8 warps); block spans all 256 rows so
// W is read from DRAM exactly once. A: coalesced LDG.128 of pre-swizzled H.
// B: ldmatrix.x4 from padded smem.
// ---------------------------------------------------------------------------
#define WPAD 132  // words per smem W row: banks = (4*row + c) % 32, conflict-free

__device__ __forceinline__ void mma_bf16(float c[4], uint32_t a0, uint32_t a1,
                                         uint32_t a2, uint32_t a3,
                                         uint32_t b0, uint32_t b1)
{
    asm volatile(
        "mma.sync.aligned.m16n8k16.row.col.f32.bf16.bf16.f32 "
        "{%0,%1,%2,%3}, {%4,%5,%6,%7}, {%8,%9}, {%0,%1,%2,%3};"
        : "+f"(c[0]), "+f"(c[1]), "+f"(c[2]), "+f"(c[3])
        : "r"(a0), "r"(a1), "r"(a2), "r"(a3), "r"(b0), "r"(b1));
}

__device__ __forceinline__ void ldsm_x4(uint32_t& r0, uint32_t& r1,
                                        uint32_t& r2, uint32_t& r3, uint32_t saddr)
{
    asm volatile("ldmatrix.sync.aligned.m8n8.x4.shared.b16 {%0,%1,%2,%3}, [%4];"
                 : "=r"(r0), "=r"(r1), "=r"(r2), "=r"(r3) : "r"(saddr));
}

__global__ void __launch_bounds__(256) logits_kernel(
    const float* __restrict__ W, const float* __restrict__ b_out,
    float* __restrict__ out)
{
    __shared__ uint32_t Wsh[64 * WPAD];

    const int n_base = blockIdx.x * 64;
    const int tid = threadIdx.x;

    // Stage W chunk [64 x 256] fp32 -> bf16 smem with float4 loads.
    {
        const float4* W4 = reinterpret_cast<const float4*>(W + (size_t)n_base * HID);
#pragma unroll 4
        for (int i = tid; i < 64 * 64; i += 256) {
            float4 v = W4[i];
            int row  = i >> 6;
            int col2 = (i & 63) * 2;
            __nv_bfloat162 lo = __floats2bfloat162_rn(v.x, v.y);
            __nv_bfloat162 hi = __floats2bfloat162_rn(v.z, v.w);
            Wsh[row * WPAD + col2]     = *reinterpret_cast<uint32_t*>(&lo);
            Wsh[row * WPAD + col2 + 1] = *reinterpret_cast<uint32_t*>(&hi);
        }
    }
    __syncthreads();

    const int warp = tid >> 5;
    const int lane = tid & 31;
    const int g  = lane >> 2;
    const int tg = lane & 3;

    // ldmatrix lane-role: matrix m = lane/8; m0=b0(nf), m1=b1(nf), m2=b0(nf+1), m3=b1(nf+1)
    const int lmRow  = ((lane >> 4) * 8) + (lane & 7);  // n-row within 16-row pair-tile
    const int lmHalf = ((lane >> 3) & 1) * 4;           // 0 (b0) or 4 (b1) k-word offset
    const uint32_t WshBase =
        (uint32_t)__cvta_generic_to_shared(Wsh) + (uint32_t)(lmRow * WPAD + lmHalf) * 4u;

    float c[2][8][4];
#pragma unroll
    for (int mf = 0; mf < 2; mf++)
#pragma unroll
        for (int nf = 0; nf < 8; nf++)
#pragma unroll
            for (int i = 0; i < 4; i++) c[mf][nf][i] = 0.f;

#pragma unroll 4
    for (int ks = 0; ks < 16; ks++) {
        const int kw = ks * 8;
        uint4 va0 = g_h0p[(((warp * 2 + 0) * 16) + ks) * 32 + lane];
        uint4 va1 = g_h0p[(((warp * 2 + 1) * 16) + ks) * 32 + lane];
#pragma unroll
        for (int nfp = 0; nfp < 4; nfp++) {
            uint32_t b0r, b1r, b2r, b3r;
            ldsm_x4(b0r, b1r, b2r, b3r,
                    WshBase + (uint32_t)(nfp * 16 * WPAD + kw) * 4u);
            mma_bf16(c[0][2 * nfp],     va0.x, va0.y, va0.z, va0.w, b0r, b1r);
            mma_bf16(c[1][2 * nfp],     va1.x, va1.y, va1.z, va1.w, b0r, b1r);
            mma_bf16(c[0][2 * nfp + 1], va0.x, va0.y, va0.z, va0.w, b2r, b3r);
            mma_bf16(c[1][2 * nfp + 1], va1.x, va1.y, va1.z, va1.w, b2r, b3r);
        }
    }

    const int m0 = warp * 32;
#pragma unroll
    for (int nf = 0; nf < 8; nf++) {
        const int n = n_base + nf * 8 + tg * 2;
        const float2 bo = *reinterpret_cast<const float2*>(b_out + n);
#pragma unroll
        for (int mf = 0; mf < 2; mf++) {
            int r0 = m0 + mf * 16 + g;
            float2 v0 = make_float2(c[mf][nf][0] + bo.x, c[mf][nf][1] + bo.y);
            float2 v1 = make_float2(c[mf][nf][2] + bo.x, c[mf][nf][3] + bo.y);
            *reinterpret_cast<float2*>(out + (size_t)(r0    ) * NCLS + n) = v0;
            *reinterpret_cast<float2*>(out + (size_t)(r0 + 8) * NCLS + n) = v1;
        }
    }
}

// ---------------------------------------------------------------------------
extern "C" void kernel_launch(void* const* d_in, const int* in_sizes, int n_in,
                              void* d_out, int out_size)
{
    const int*   X       = (const int*)  d_in[0];
    const float* C_table = (const float*)d_in[1];
    const float* U_i     = (const float*)d_in[2];
    const float* b_i     = (const float*)d_in[4];
    const float* U_c     = (const float*)d_in[8];
    const float* b_c     = (const float*)d_in[10];
    const float* U_o     = (const float*)d_in[11];
    const float* b_o     = (const float*)d_in[13];
    const float* W_w     = (const float*)d_in[26];
    const float* b_out   = (const float*)d_in[27];
    float* out = (float*)d_out;

    lstm0_kernel<<<32, 256>>>(X, C_table, U_i, b_i, U_c, b_c, U_o, b_o);
    logits_kernel<<<NCLS / 64, 256>>>(W_w, b_out, out);
}

// round 3
// speedup vs baseline: 1.4007x; 1.0944x over previous
#include <cuda_runtime.h>
#include <cuda_bf16.h>
#include <cstdint>

// Problem dims
#define BB   256
#define TT   512
#define EMB  128
#define HID  256
#define NCLS 32000

// H pre-swizzled into mma A-fragment order.
// [m_tile(16)][ks(16)][lane(32)] of uint4 = {a0,a1,a2,a3} bf16x2 words:
//   a0 = word(R+g,   KW+tg)   a1 = word(R+8+g, KW+tg)
//   a2 = word(R+g,   KW+4+tg) a3 = word(R+8+g, KW+4+tg)
__device__ uint4 g_h0p[16 * 16 * 32];   // 128 KB

// ---------------------------------------------------------------------------
// Kernel A: layer-0 LSTM (no recurrence), h-split 4-way for occupancy.
// grid (32 row-blocks, 4 h-blocks) x 256 thr. Block: 8 batch rows x 64 h.
// Thread = (row_group rg of 2 rows, h_local).
// ---------------------------------------------------------------------------
__global__ void __launch_bounds__(256) lstm0_kernel(
    const int* __restrict__ X, const float* __restrict__ C_table,
    const float* __restrict__ U_i, const float* __restrict__ b_i,
    const float* __restrict__ U_c, const float* __restrict__ b_c,
    const float* __restrict__ U_o, const float* __restrict__ b_o)
{
    __shared__ int   toks[8];
    __shared__ float Esh[8][EMB];
    __shared__ float Hsh[8][64];
    const int b0 = blockIdx.x * 8;
    const int hb = blockIdx.y * 64;
    const int t  = threadIdx.x;

    if (t < 8) toks[t] = X[(b0 + t) * TT + (TT - 1)];
    __syncthreads();
#pragma unroll
    for (int j = 0; j < 4; j++) {
        int idx = t + 256 * j;       // 0..1023
        int r = idx >> 7, e = idx & 127;
        Esh[r][e] = C_table[toks[r] * EMB + e];
    }
    __syncthreads();

    const int h_local = t & 63;
    const int rg      = t >> 6;      // 0..3 -> rows 2rg, 2rg+1
    const int h       = hb + h_local;
    const int r0 = rg * 2, r1 = rg * 2 + 1;

    float ai0 = 0.f, ai1 = 0.f, ac0 = 0.f, ac1 = 0.f, ao0 = 0.f, ao1 = 0.f;
#pragma unroll 8
    for (int e = 0; e < EMB; e++) {
        float ui = U_i[e * HID + h];
        float uc = U_c[e * HID + h];
        float uo = U_o[e * HID + h];
        float e0 = Esh[r0][e], e1 = Esh[r1][e];
        ai0 = fmaf(e0, ui, ai0); ai1 = fmaf(e1, ui, ai1);
        ac0 = fmaf(e0, uc, ac0); ac1 = fmaf(e1, uc, ac1);
        ao0 = fmaf(e0, uo, ao0); ao1 = fmaf(e1, uo, ao1);
    }

    const float bi = b_i[h], bc = b_c[h], bo = b_o[h];
    {
        float i0 = 1.f / (1.f + expf(-(ai0 + bi)));
        float g0 = tanhf(ac0 + bc);
        float o0 = 1.f / (1.f + expf(-(ao0 + bo)));
        Hsh[r0][h_local] = o0 * tanhf(i0 * g0);
        float i1 = 1.f / (1.f + expf(-(ai1 + bi)));
        float g1 = tanhf(ac1 + bc);
        float o1 = 1.f / (1.f + expf(-(ao1 + bo)));
        Hsh[r1][h_local] = o1 * tanhf(i1 * g1);
    }
    __syncthreads();

    // Pack: 8 rows x 32 bf16x2 words (this block's h-slice) -> fragment layout.
    uint32_t* Hw = reinterpret_cast<uint32_t*>(g_h0p);
    {
        int r  = t >> 5;             // 0..7
        int wl = t & 31;             // local word
        int w  = (hb >> 1) + wl;     // global k-word 0..127
        int gr = b0 + r;
        int m_tile = gr >> 4;
        int local  = gr & 15;
        int g      = local & 7;
        int comp_r = local >> 3;
        int ks     = w >> 3;
        int ww     = w & 7;
        int tg     = ww & 3;
        int comp_k = (ww >> 2) << 1;
        int lane   = g * 4 + tg;
        __nv_bfloat162 bv = __floats2bfloat162_rn(Hsh[r][2 * wl], Hsh[r][2 * wl + 1]);
        Hw[((((m_tile * 16) + ks) * 32 + lane) << 2) + (comp_r + comp_k)] =
            *reinterpret_cast<uint32_t*>(&bv);
    }
}

// ---------------------------------------------------------------------------
// Kernel B: out = h0 @ W_w^T + b_out via bf16 mma.sync
// 500 blocks (64 classes) x 512 threads (16 warps). Warp w = 16-row m-tile.
// Target 2 blocks/SM (50% occ) for latency hiding.
// ---------------------------------------------------------------------------
#define WPAD 132

__device__ __forceinline__ void mma_bf16(float c[4], uint32_t a0, uint32_t a1,
                                         uint32_t a2, uint32_t a3,
                                         uint32_t b0, uint32_t b1)
{
    asm volatile(
        "mma.sync.aligned.m16n8k16.row.col.f32.bf16.bf16.f32 "
        "{%0,%1,%2,%3}, {%4,%5,%6,%7}, {%8,%9}, {%0,%1,%2,%3};"
        : "+f"(c[0]), "+f"(c[1]), "+f"(c[2]), "+f"(c[3])
        : "r"(a0), "r"(a1), "r"(a2), "r"(a3), "r"(b0), "r"(b1));
}

__device__ __forceinline__ void ldsm_x4(uint32_t& r0, uint32_t& r1,
                                        uint32_t& r2, uint32_t& r3, uint32_t saddr)
{
    asm volatile("ldmatrix.sync.aligned.m8n8.x4.shared.b16 {%0,%1,%2,%3}, [%4];"
                 : "=r"(r0), "=r"(r1), "=r"(r2), "=r"(r3) : "r"(saddr));
}

__global__ void __launch_bounds__(512, 2) logits_kernel(
    const float* __restrict__ W, const float* __restrict__ b_out,
    float* __restrict__ out)
{
    __shared__ uint32_t Wsh[64 * WPAD];

    const int n_base = blockIdx.x * 64;
    const int tid = threadIdx.x;

    // Stage W chunk [64 x 256] fp32 -> bf16 smem with float4 loads.
    {
        const float4* W4 = reinterpret_cast<const float4*>(W + (size_t)n_base * HID);
#pragma unroll
        for (int j = 0; j < 8; j++) {
            int i = tid + 512 * j;   // 0..4095
            float4 v = W4[i];
            int row  = i >> 6;
            int col2 = (i & 63) * 2;
            __nv_bfloat162 lo = __floats2bfloat162_rn(v.x, v.y);
            __nv_bfloat162 hi = __floats2bfloat162_rn(v.z, v.w);
            Wsh[row * WPAD + col2]     = *reinterpret_cast<uint32_t*>(&lo);
            Wsh[row * WPAD + col2 + 1] = *reinterpret_cast<uint32_t*>(&hi);
        }
    }
    __syncthreads();

    const int warp = tid >> 5;   // m-tile 0..15
    const int lane = tid & 31;
    const int g  = lane >> 2;
    const int tg = lane & 3;

    const int lmRow  = ((lane >> 4) * 8) + (lane & 7);
    const int lmHalf = ((lane >> 3) & 1) * 4;
    const uint32_t WshBase =
        (uint32_t)__cvta_generic_to_shared(Wsh) + (uint32_t)(lmRow * WPAD + lmHalf) * 4u;

    float c[8][4];
#pragma unroll
    for (int nf = 0; nf < 8; nf++)
#pragma unroll
        for (int i = 0; i < 4; i++) c[nf][i] = 0.f;

#pragma unroll 4
    for (int ks = 0; ks < 16; ks++) {
        uint4 va = g_h0p[((warp * 16) + ks) * 32 + lane];
        const uint32_t kwb = (uint32_t)(ks * 8) * 4u;
#pragma unroll
        for (int nfp = 0; nfp < 4; nfp++) {
            uint32_t b0r, b1r, b2r, b3r;
            ldsm_x4(b0r, b1r, b2r, b3r,
                    WshBase + (uint32_t)(nfp * 16 * WPAD) * 4u + kwb);
            mma_bf16(c[2 * nfp],     va.x, va.y, va.z, va.w, b0r, b1r);
            mma_bf16(c[2 * nfp + 1], va.x, va.y, va.z, va.w, b2r, b3r);
        }
    }

    const int r0 = warp * 16 + g;
#pragma unroll
    for (int nf = 0; nf < 8; nf++) {
        const int n = n_base + nf * 8 + tg * 2;
        const float2 bo = *reinterpret_cast<const float2*>(b_out + n);
        float2 v0 = make_float2(c[nf][0] + bo.x, c[nf][1] + bo.y);
        float2 v1 = make_float2(c[nf][2] + bo.x, c[nf][3] + bo.y);
        *reinterpret_cast<float2*>(out + (size_t)(r0    ) * NCLS + n) = v0;
        *reinterpret_cast<float2*>(out + (size_t)(r0 + 8) * NCLS + n) = v1;
    }
}

// ---------------------------------------------------------------------------
extern "C" void kernel_launch(void* const* d_in, const int* in_sizes, int n_in,
                              void* d_out, int out_size)
{
    const int*   X       = (const int*)  d_in[0];
    const float* C_table = (const float*)d_in[1];
    const float* U_i     = (const float*)d_in[2];
    const float* b_i     = (const float*)d_in[4];
    const float* U_c     = (const float*)d_in[8];
    const float* b_c     = (const float*)d_in[10];
    const float* U_o     = (const float*)d_in[11];
    const float* b_o     = (const float*)d_in[13];
    const float* W_w     = (const float*)d_in[26];
    const float* b_out   = (const float*)d_in[27];
    float* out = (float*)d_out;

    lstm0_kernel<<<dim3(32, 4), 256>>>(X, C_table, U_i, b_i, U_c, b_c, U_o, b_o);
    logits_kernel<<<NCLS / 64, 512>>>(W_w, b_out, out);
}

// round 4
// speedup vs baseline: 1.6213x; 1.1575x over previous
#include <cuda_runtime.h>
#include <cuda_bf16.h>
#include <cstdint>

// Problem dims
#define BB   256
#define TT   512
#define EMB  128
#define HID  256
#define NCLS 32000

#define NBLK 250   // persistent grid size (<= 296 co-resident capacity)

// H pre-swizzled into mma A-fragment order.
// [m_tile(16)][ks(16)][lane(32)] of uint4 = {a0,a1,a2,a3} bf16x2 words.
__device__ uint4 g_h0p[16 * 16 * 32];   // 128 KB

// Monotonic ticket barrier (graph-replay safe: never reset).
__device__ unsigned int g_bar;

#define WPAD 132

__device__ __forceinline__ void mma_bf16(float c[4], uint32_t a0, uint32_t a1,
                                         uint32_t a2, uint32_t a3,
                                         uint32_t b0, uint32_t b1)
{
    asm volatile(
        "mma.sync.aligned.m16n8k16.row.col.f32.bf16.bf16.f32 "
        "{%0,%1,%2,%3}, {%4,%5,%6,%7}, {%8,%9}, {%0,%1,%2,%3};"
        : "+f"(c[0]), "+f"(c[1]), "+f"(c[2]), "+f"(c[3])
        : "r"(a0), "r"(a1), "r"(a2), "r"(a3), "r"(b0), "r"(b1));
}

__device__ __forceinline__ void ldsm_x4(uint32_t& r0, uint32_t& r1,
                                        uint32_t& r2, uint32_t& r3, uint32_t saddr)
{
    asm volatile("ldmatrix.sync.aligned.m8n8.x4.shared.b16 {%0,%1,%2,%3}, [%4];"
                 : "=r"(r0), "=r"(r1), "=r"(r2), "=r"(r3) : "r"(saddr));
}

__global__ void __launch_bounds__(512, 2) fused_kernel(
    const int* __restrict__ X, const float* __restrict__ C_table,
    const float* __restrict__ U_i, const float* __restrict__ b_i,
    const float* __restrict__ U_c, const float* __restrict__ b_c,
    const float* __restrict__ U_o, const float* __restrict__ b_o,
    const float* __restrict__ W, const float* __restrict__ b_out,
    float* __restrict__ out)
{
    __shared__ uint32_t Wsh[64 * WPAD];            // 33.8 KB (phase 2)
    __shared__ float    Esh[4][4][EMB];            // 8 KB   (phase 1)
    __shared__ float    Hsh[4][4][64];             // 4 KB   (phase 1)
    __shared__ int      toks[4][4];

    const int tid = threadIdx.x;

    // ===================== Phase 1: layer-0 LSTM + fragment pack ==========
    // 256 virtual tiles (4 rows x 64 h), spread over all blocks:
    // vb = blockIdx.x + 250*grp  (grp = tid/128), active iff vb < 256.
    {
        const int grp  = tid >> 7;        // 0..3
        const int gtid = tid & 127;
        const int vb   = blockIdx.x + NBLK * grp;
        const bool act = (vb < 256);

        int row_block = vb & 63;          // 64 row-blocks of 4 rows
        int h_block   = vb >> 6;          // 4 h-blocks of 64
        int b0 = row_block * 4;
        int hb = h_block * 64;

        if (act) {
            if (gtid < 4) toks[grp][gtid] = X[(b0 + gtid) * TT + (TT - 1)];
        }
        __syncthreads();
        if (act) {
#pragma unroll
            for (int j = 0; j < 4; j++) {
                int idx = gtid + 128 * j;       // 0..511
                int r = idx >> 7, e = idx & 127;
                Esh[grp][r][e] = C_table[toks[grp][r] * EMB + e];
            }
        }
        __syncthreads();

        if (act) {
            const int h_local = gtid & 63;
            const int rp      = gtid >> 6;      // 0..1 -> rows 2rp, 2rp+1
            const int h       = hb + h_local;
            const int r0 = rp * 2, r1 = rp * 2 + 1;

            float ai0 = 0.f, ai1 = 0.f, ac0 = 0.f, ac1 = 0.f, ao0 = 0.f, ao1 = 0.f;
#pragma unroll 8
            for (int e = 0; e < EMB; e++) {
                float ui = U_i[e * HID + h];
                float uc = U_c[e * HID + h];
                float uo = U_o[e * HID + h];
                float e0 = Esh[grp][r0][e], e1 = Esh[grp][r1][e];
                ai0 = fmaf(e0, ui, ai0); ai1 = fmaf(e1, ui, ai1);
                ac0 = fmaf(e0, uc, ac0); ac1 = fmaf(e1, uc, ac1);
                ao0 = fmaf(e0, uo, ao0); ao1 = fmaf(e1, uo, ao1);
            }
            const float bi = b_i[h], bc = b_c[h], bo = b_o[h];
            float i0 = 1.f / (1.f + expf(-(ai0 + bi)));
            float g0 = tanhf(ac0 + bc);
            float o0 = 1.f / (1.f + expf(-(ao0 + bo)));
            Hsh[grp][r0][h_local] = o0 * tanhf(i0 * g0);
            float i1 = 1.f / (1.f + expf(-(ai1 + bi)));
            float g1 = tanhf(ac1 + bc);
            float o1 = 1.f / (1.f + expf(-(ao1 + bo)));
            Hsh[grp][r1][h_local] = o1 * tanhf(i1 * g1);
        }
        __syncthreads();

        if (act) {
            // Pack: 4 rows x 32 bf16x2 words -> fragment layout. One word/thread.
            uint32_t* Hw = reinterpret_cast<uint32_t*>(g_h0p);
            int r  = gtid >> 5;                  // 0..3
            int wl = gtid & 31;
            int w  = h_block * 32 + wl;          // global k-word 0..127
            int gr = b0 + r;
            int m_tile = gr >> 4;
            int local  = gr & 15;
            int g      = local & 7;
            int comp_r = local >> 3;
            int ks     = w >> 3;
            int ww     = w & 7;
            int tg     = ww & 3;
            int comp_k = (ww >> 2) << 1;
            int lane   = g * 4 + tg;
            __nv_bfloat162 bv =
                __floats2bfloat162_rn(Hsh[grp][r][2 * wl], Hsh[grp][r][2 * wl + 1]);
            Hw[((((m_tile * 16) + ks) * 32 + lane) << 2) + (comp_r + comp_k)] =
                *reinterpret_cast<uint32_t*>(&bv);
        }
    }

    // ===================== Global barrier (release/acquire) ===============
    __threadfence();
    __syncthreads();
    if (tid == 0) {
        unsigned int t = atomicAdd(&g_bar, 1u);
        unsigned int target = (t / NBLK + 1u) * NBLK;
        while (*((volatile unsigned int*)&g_bar) < target) { __nanosleep(64); }
    }
    __syncthreads();
    __threadfence();

    // ===================== Phase 2: logits = H @ W^T + b ==================
    const int warp = tid >> 5;   // m-tile 0..15
    const int lane = tid & 31;
    const int g  = lane >> 2;
    const int tg = lane & 3;

    const int lmRow  = ((lane >> 4) * 8) + (lane & 7);
    const int lmHalf = ((lane >> 3) & 1) * 4;
    const uint32_t WshBase =
        (uint32_t)__cvta_generic_to_shared(Wsh) + (uint32_t)(lmRow * WPAD + lmHalf) * 4u;

#pragma unroll 1
    for (int chunk = 0; chunk < 2; chunk++) {
        const int n_base = (blockIdx.x + chunk * NBLK) * 64;

        // Stage W chunk [64 x 256] fp32 -> bf16 smem with float4 loads.
        {
            const float4* W4 = reinterpret_cast<const float4*>(W + (size_t)n_base * HID);
#pragma unroll
            for (int j = 0; j < 8; j++) {
                int i = tid + 512 * j;   // 0..4095
                float4 v = W4[i];
                int row  = i >> 6;
                int col2 = (i & 63) * 2;
                __nv_bfloat162 lo = __floats2bfloat162_rn(v.x, v.y);
                __nv_bfloat162 hi = __floats2bfloat162_rn(v.z, v.w);
                Wsh[row * WPAD + col2]     = *reinterpret_cast<uint32_t*>(&lo);
                Wsh[row * WPAD + col2 + 1] = *reinterpret_cast<uint32_t*>(&hi);
            }
        }
        __syncthreads();

        float c[8][4];
#pragma unroll
        for (int nf = 0; nf < 8; nf++)
#pragma unroll
            for (int i = 0; i < 4; i++) c[nf][i] = 0.f;

#pragma unroll 4
        for (int ks = 0; ks < 16; ks++) {
            uint4 va = g_h0p[((warp * 16) + ks) * 32 + lane];
            const uint32_t kwb = (uint32_t)(ks * 8) * 4u;
#pragma unroll
            for (int nfp = 0; nfp < 4; nfp++) {
                uint32_t b0r, b1r, b2r, b3r;
                ldsm_x4(b0r, b1r, b2r, b3r,
                        WshBase + (uint32_t)(nfp * 16 * WPAD) * 4u + kwb);
                mma_bf16(c[2 * nfp],     va.x, va.y, va.z, va.w, b0r, b1r);
                mma_bf16(c[2 * nfp + 1], va.x, va.y, va.z, va.w, b2r, b3r);
            }
        }

        const int r0 = warp * 16 + g;
#pragma unroll
        for (int nf = 0; nf < 8; nf++) {
            const int n = n_base + nf * 8 + tg * 2;
            const float2 bo = *reinterpret_cast<const float2*>(b_out + n);
            float2 v0 = make_float2(c[nf][0] + bo.x, c[nf][1] + bo.y);
            float2 v1 = make_float2(c[nf][2] + bo.x, c[nf][3] + bo.y);
            *reinterpret_cast<float2*>(out + (size_t)(r0    ) * NCLS + n) = v0;
            *reinterpret_cast<float2*>(out + (size_t)(r0 + 8) * NCLS + n) = v1;
        }
        __syncthreads();   // before restaging Wsh for next chunk
    }
}

// ---------------------------------------------------------------------------
extern "C" void kernel_launch(void* const* d_in, const int* in_sizes, int n_in,
                              void* d_out, int out_size)
{
    const int*   X       = (const int*)  d_in[0];
    const float* C_table = (const float*)d_in[1];
    const float* U_i     = (const float*)d_in[2];
    const float* b_i     = (const float*)d_in[4];
    const float* U_c     = (const float*)d_in[8];
    const float* b_c     = (const float*)d_in[10];
    const float* U_o     = (const float*)d_in[11];
    const float* b_o     = (const float*)d_in[13];
    const float* W_w     = (const float*)d_in[26];
    const float* b_out   = (const float*)d_in[27];
    float* out = (float*)d_out;

    fused_kernel<<<NBLK, 512>>>(X, C_table, U_i, b_i, U_c, b_c, U_o, b_o,
                                W_w, b_out, out);
}

// round 5
// speedup vs baseline: 1.6628x; 1.0256x over previous
#include <cuda_runtime.h>
#include <cuda_bf16.h>
#include <cstdint>

// Problem dims
#define BB   256
#define TT   512
#define EMB  128
#define HID  256
#define NCLS 32000

#define NBLK 250   // persistent grid size (co-resident)
#define WPAD 132   // bf16x2 words per smem W row (conflict-free ldmatrix)

// Dynamic smem layout (per block):
//   [0,       65536)  : fp32 W stage buffer (64 rows x 256 floats)
//   [65536,   99328)  : Wsh bf16x2 [64][WPAD]  (phase 1 unions Esh/Hsh/toks here)
#define SMEM_BYTES (65536 + 64 * WPAD * 4)

// H pre-swizzled into mma A-fragment order: [m_tile(16)][ks(16)][lane(32)] uint4.
__device__ uint4 g_h0p[16 * 16 * 32];   // 128 KB

// Monotonic ticket barrier (graph-replay safe: never reset).
__device__ unsigned int g_bar;

__device__ __forceinline__ void mma_bf16(float c[4], uint32_t a0, uint32_t a1,
                                         uint32_t a2, uint32_t a3,
                                         uint32_t b0, uint32_t b1)
{
    asm volatile(
        "mma.sync.aligned.m16n8k16.row.col.f32.bf16.bf16.f32 "
        "{%0,%1,%2,%3}, {%4,%5,%6,%7}, {%8,%9}, {%0,%1,%2,%3};"
        : "+f"(c[0]), "+f"(c[1]), "+f"(c[2]), "+f"(c[3])
        : "r"(a0), "r"(a1), "r"(a2), "r"(a3), "r"(b0), "r"(b1));
}

__device__ __forceinline__ void ldsm_x4(uint32_t& r0, uint32_t& r1,
                                        uint32_t& r2, uint32_t& r3, uint32_t saddr)
{
    asm volatile("ldmatrix.sync.aligned.m8n8.x4.shared.b16 {%0,%1,%2,%3}, [%4];"
                 : "=r"(r0), "=r"(r1), "=r"(r2), "=r"(r3) : "r"(saddr));
}

__device__ __forceinline__ void cp_async16(uint32_t saddr, const void* gaddr)
{
    asm volatile("cp.async.cg.shared.global [%0], [%1], 16;"
                 :: "r"(saddr), "l"(gaddr));
}

__global__ void __launch_bounds__(512, 2) fused_kernel(
    const int* __restrict__ X, const float* __restrict__ C_table,
    const float* __restrict__ U_i, const float* __restrict__ b_i,
    const float* __restrict__ U_c, const float* __restrict__ b_c,
    const float* __restrict__ U_o, const float* __restrict__ b_o,
    const float* __restrict__ W, const float* __restrict__ b_out,
    float* __restrict__ out)
{
    extern __shared__ char smem_raw[];
    float4*   stage = reinterpret_cast<float4*>(smem_raw);              // 64 KB
    uint32_t* Wsh   = reinterpret_cast<uint32_t*>(smem_raw + 65536);    // 33.8 KB
    // Phase-1 overlays on the Wsh region (disjoint lifetime):
    float (*Esh)[4][EMB] = reinterpret_cast<float(*)[4][EMB]>(smem_raw + 65536);
    float (*Hsh)[4][64]  = reinterpret_cast<float(*)[4][64]>(smem_raw + 65536 + 8192);
    int   (*toks)[4]     = reinterpret_cast<int(*)[4]>(smem_raw + 65536 + 8192 + 4096);

    const int tid = threadIdx.x;
    const uint32_t stage_base = (uint32_t)__cvta_generic_to_shared(stage);

    // ------ Issue chunk-0 W fetch immediately (independent of phase 1) -----
    {
        const float4* W4 = reinterpret_cast<const float4*>(W + (size_t)blockIdx.x * 64 * HID);
#pragma unroll
        for (int j = 0; j < 8; j++) {
            int i = tid + 512 * j;
            cp_async16(stage_base + (uint32_t)i * 16u, W4 + i);
        }
        asm volatile("cp.async.commit_group;");
    }

    // ===================== Phase 1: layer-0 LSTM + fragment pack ==========
    {
        const int grp  = tid >> 7;        // 0..3
        const int gtid = tid & 127;
        const int vb   = blockIdx.x + NBLK * grp;
        const bool act = (vb < 256);

        int row_block = vb & 63;
        int h_block   = vb >> 6;
        int b0 = row_block * 4;
        int hb = h_block * 64;

        if (act && gtid < 4) toks[grp][gtid] = X[(b0 + gtid) * TT + (TT - 1)];
        __syncthreads();
        if (act) {
#pragma unroll
            for (int j = 0; j < 4; j++) {
                int idx = gtid + 128 * j;
                int r = idx >> 7, e = idx & 127;
                Esh[grp][r][e] = C_table[toks[grp][r] * EMB + e];
            }
        }
        __syncthreads();

        if (act) {
            const int h_local = gtid & 63;
            const int rp      = gtid >> 6;
            const int h       = hb + h_local;
            const int r0 = rp * 2, r1 = rp * 2 + 1;

            float ai0 = 0.f, ai1 = 0.f, ac0 = 0.f, ac1 = 0.f, ao0 = 0.f, ao1 = 0.f;
#pragma unroll 8
            for (int e = 0; e < EMB; e++) {
                float ui = U_i[e * HID + h];
                float uc = U_c[e * HID + h];
                float uo = U_o[e * HID + h];
                float e0 = Esh[grp][r0][e], e1 = Esh[grp][r1][e];
                ai0 = fmaf(e0, ui, ai0); ai1 = fmaf(e1, ui, ai1);
                ac0 = fmaf(e0, uc, ac0); ac1 = fmaf(e1, uc, ac1);
                ao0 = fmaf(e0, uo, ao0); ao1 = fmaf(e1, uo, ao1);
            }
            const float bi = b_i[h], bc = b_c[h], bo = b_o[h];
            float i0 = 1.f / (1.f + expf(-(ai0 + bi)));
            float g0 = tanhf(ac0 + bc);
            float o0 = 1.f / (1.f + expf(-(ao0 + bo)));
            Hsh[grp][r0][h_local] = o0 * tanhf(i0 * g0);
            float i1 = 1.f / (1.f + expf(-(ai1 + bi)));
            float g1 = tanhf(ac1 + bc);
            float o1 = 1.f / (1.f + expf(-(ao1 + bo)));
            Hsh[grp][r1][h_local] = o1 * tanhf(i1 * g1);
        }
        __syncthreads();

        if (act) {
            uint32_t* Hw = reinterpret_cast<uint32_t*>(g_h0p);
            int r  = gtid >> 5;
            int wl = gtid & 31;
            int w  = h_block * 32 + wl;
            int gr = b0 + r;
            int m_tile = gr >> 4;
            int local  = gr & 15;
            int g      = local & 7;
            int comp_r = local >> 3;
            int ks     = w >> 3;
            int ww     = w & 7;
            int tg     = ww & 3;
            int comp_k = (ww >> 2) << 1;
            int lane   = g * 4 + tg;
            __nv_bfloat162 bv =
                __floats2bfloat162_rn(Hsh[grp][r][2 * wl], Hsh[grp][r][2 * wl + 1]);
            Hw[((((m_tile * 16) + ks) * 32 + lane) << 2) + (comp_r + comp_k)] =
                *reinterpret_cast<uint32_t*>(&bv);
        }
        __syncthreads();   // phase-1 smem region free for reuse as Wsh
    }

    // ------ Wait chunk-0 W, convert stage -> Wsh (bf16) -------------------
    asm volatile("cp.async.wait_group 0;");
    __syncthreads();
#pragma unroll
    for (int j = 0; j < 8; j++) {
        int i = tid + 512 * j;
        float4 v = stage[i];
        int row  = i >> 6;
        int col2 = (i & 63) * 2;
        __nv_bfloat162 lo = __floats2bfloat162_rn(v.x, v.y);
        __nv_bfloat162 hi = __floats2bfloat162_rn(v.z, v.w);
        Wsh[row * WPAD + col2]     = *reinterpret_cast<uint32_t*>(&lo);
        Wsh[row * WPAD + col2 + 1] = *reinterpret_cast<uint32_t*>(&hi);
    }
    __syncthreads();

    // ===================== Global barrier (release/acquire) ===============
    __threadfence();
    if (tid == 0) {
        unsigned int t = atomicAdd(&g_bar, 1u);
        unsigned int target = (t / NBLK + 1u) * NBLK;
        while (*((volatile unsigned int*)&g_bar) < target) { __nanosleep(64); }
    }
    __syncthreads();
    __threadfence();

    // ------ Issue chunk-1 W fetch (overlaps chunk-0 compute) --------------
    {
        const float4* W4 = reinterpret_cast<const float4*>(
            W + (size_t)(blockIdx.x + NBLK) * 64 * HID);
#pragma unroll
        for (int j = 0; j < 8; j++) {
            int i = tid + 512 * j;
            cp_async16(stage_base + (uint32_t)i * 16u, W4 + i);
        }
        asm volatile("cp.async.commit_group;");
    }

    // ===================== Phase 2: logits = H @ W^T + b ==================
    const int warp = tid >> 5;
    const int lane = tid & 31;
    const int g  = lane >> 2;
    const int tg = lane & 3;

    const int lmRow  = ((lane >> 4) * 8) + (lane & 7);
    const int lmHalf = ((lane >> 3) & 1) * 4;
    const uint32_t WshBase =
        (uint32_t)__cvta_generic_to_shared(Wsh) + (uint32_t)(lmRow * WPAD + lmHalf) * 4u;

#pragma unroll 1
    for (int chunk = 0; chunk < 2; chunk++) {
        const int n_base = (blockIdx.x + chunk * NBLK) * 64;

        float c[8][4];
#pragma unroll
        for (int nf = 0; nf < 8; nf++)
#pragma unroll
            for (int i = 0; i < 4; i++) c[nf][i] = 0.f;

#pragma unroll 4
        for (int ks = 0; ks < 16; ks++) {
            uint4 va = g_h0p[((warp * 16) + ks) * 32 + lane];
            const uint32_t kwb = (uint32_t)(ks * 8) * 4u;
#pragma unroll
            for (int nfp = 0; nfp < 4; nfp++) {
                uint32_t b0r, b1r, b2r, b3r;
                ldsm_x4(b0r, b1r, b2r, b3r,
                        WshBase + (uint32_t)(nfp * 16 * WPAD) * 4u + kwb);
                mma_bf16(c[2 * nfp],     va.x, va.y, va.z, va.w, b0r, b1r);
                mma_bf16(c[2 * nfp + 1], va.x, va.y, va.z, va.w, b2r, b3r);
            }
        }

        const int r0 = warp * 16 + g;
#pragma unroll
        for (int nf = 0; nf < 8; nf++) {
            const int n = n_base + nf * 8 + tg * 2;
            const float2 bo = *reinterpret_cast<const float2*>(b_out + n);
            float2 v0 = make_float2(c[nf][0] + bo.x, c[nf][1] + bo.y);
            float2 v1 = make_float2(c[nf][2] + bo.x, c[nf][3] + bo.y);
            *reinterpret_cast<float2*>(out + (size_t)(r0    ) * NCLS + n) = v0;
            *reinterpret_cast<float2*>(out + (size_t)(r0 + 8) * NCLS + n) = v1;
        }

        if (chunk == 0) {
            // Retire chunk-1 fetch, convert into Wsh for the second pass.
            __syncthreads();                       // all reads of Wsh chunk0 done
            asm volatile("cp.async.wait_group 0;");
            __syncthreads();
#pragma unroll
            for (int j = 0; j < 8; j++) {
                int i = tid + 512 * j;
                float4 v = stage[i];
                int row  = i >> 6;
                int col2 = (i & 63) * 2;
                __nv_bfloat162 lo = __floats2bfloat162_rn(v.x, v.y);
                __nv_bfloat162 hi = __floats2bfloat162_rn(v.z, v.w);
                Wsh[row * WPAD + col2]     = *reinterpret_cast<uint32_t*>(&lo);
                Wsh[row * WPAD + col2 + 1] = *reinterpret_cast<uint32_t*>(&hi);
            }
            __syncthreads();
        }
    }
}

// ---------------------------------------------------------------------------
extern "C" void kernel_launch(void* const* d_in, const int* in_sizes, int n_in,
                              void* d_out, int out_size)
{
    const int*   X       = (const int*)  d_in[0];
    const float* C_table = (const float*)d_in[1];
    const float* U_i     = (const float*)d_in[2];
    const float* b_i     = (const float*)d_in[4];
    const float* U_c     = (const float*)d_in[8];
    const float* b_c     = (const float*)d_in[10];
    const float* U_o     = (const float*)d_in[11];
    const float* b_o     = (const float*)d_in[13];
    const float* W_w     = (const float*)d_in[26];
    const float* b_out   = (const float*)d_in[27];
    float* out = (float*)d_out;

    // Idempotent; first (uncaptured) call sets it, later calls are no-ops.
    cudaFuncSetAttribute(fused_kernel,
                         cudaFuncAttributeMaxDynamicSharedMemorySize, SMEM_BYTES);

    fused_kernel<<<NBLK, 512, SMEM_BYTES>>>(X, C_table, U_i, b_i, U_c, b_c,
                                            U_o, b_o, W_w, b_out, out);
}